// round 1
// baseline (speedup 1.0000x reference)
#include <cuda_runtime.h>

#define NQ 12

__global__ __launch_bounds__(256)
void quantum_layer_kernel(const float* __restrict__ x,
                          const float* __restrict__ w,
                          float* __restrict__ out,
                          int B)
{
    int b = blockIdx.x * blockDim.x + threadIdx.x;
    if (b >= B) return;

    // Row is 12 floats = 48 bytes, 16B-aligned -> 3x float4
    const float4* xr = reinterpret_cast<const float4*>(x + (size_t)b * NQ);
    float4 v0 = xr[0];
    float4 v1 = xr[1];
    float4 v2 = xr[2];

    float xv[NQ] = { v0.x, v0.y, v0.z, v0.w,
                     v1.x, v1.y, v1.z, v1.w,
                     v2.x, v2.y, v2.z, v2.w };

    // a = 2*atan(tanh(x)):  cos a = (1-t^2)/(1+t^2),  sin a = 2t/(1+t^2)
    float ca[NQ], sa[NQ];
#pragma unroll
    for (int q = 0; q < NQ; q++) {
        float t  = tanhf(xv[q]);
        float t2 = t * t;
        float inv = __frcp_rn(1.0f + t2);
        ca[q] = (1.0f - t2) * inv;
        sa[q] = 2.0f * t * inv;
    }

    // out_q = cos(w_q) * prod_{p<=q} cos(a_p) - sin(w_q) * S_q
    // S_q = sa[q]*sa[q+1] (q < NQ-1),  S_{NQ-1} = sa[NQ-1]
    float o[NQ];
    float prodc = 1.0f;
#pragma unroll
    for (int q = 0; q < NQ; q++) {
        prodc *= ca[q];
        float cw, sw;
        sincosf(w[q], &sw, &cw);              // uniform across threads; L2/const-cached
        float S = (q < NQ - 1) ? sa[q] * sa[q + 1] : sa[q];
        o[q] = cw * prodc - sw * S;
    }

    float4* orow = reinterpret_cast<float4*>(out + (size_t)b * NQ);
    orow[0] = make_float4(o[0], o[1], o[2],  o[3]);
    orow[1] = make_float4(o[4], o[5], o[6],  o[7]);
    orow[2] = make_float4(o[8], o[9], o[10], o[11]);
}

extern "C" void kernel_launch(void* const* d_in, const int* in_sizes, int n_in,
                              void* d_out, int out_size)
{
    const float* x = (const float*)d_in[0];   // [B, 12]
    const float* w = (const float*)d_in[1];   // [36], only first 12 used
    float* out = (float*)d_out;               // [B, 12]
    int B = in_sizes[0] / NQ;

    int threads = 256;
    int blocks = (B + threads - 1) / threads;
    quantum_layer_kernel<<<blocks, threads>>>(x, w, out, B);
}

// round 2
// speedup vs baseline: 1.2404x; 1.2404x over previous
#include <cuda_runtime.h>

#define NQ 12

__device__ __forceinline__ float ex2f(float a) {
    float r; asm("ex2.approx.f32 %0, %1;" : "=f"(r) : "f"(a)); return r;
}
__device__ __forceinline__ float rcpf(float a) {
    float r; asm("rcp.approx.f32 %0, %1;" : "=f"(r) : "f"(a)); return r;
}

__global__ __launch_bounds__(128)
void quantum_layer_kernel(const float* __restrict__ x,
                          const float* __restrict__ w,
                          float* __restrict__ out,
                          int B)
{
    __shared__ float s_cw[NQ], s_sw[NQ];
    if (threadIdx.x < NQ) {
        float s, c;
        sincosf(__ldg(&w[threadIdx.x]), &s, &c);
        s_sw[threadIdx.x] = s;
        s_cw[threadIdx.x] = c;
    }

    int b = blockIdx.x * blockDim.x + threadIdx.x;
    bool active = (b < B);
    int bb = active ? b : 0;

    // Row = 12 floats = 48B, 16B aligned -> 3x float4, coalesced.
    const float4* xr = reinterpret_cast<const float4*>(x + (size_t)bb * NQ);
    float4 v0 = xr[0];
    float4 v1 = xr[1];
    float4 v2 = xr[2];
    float xv[NQ] = { v0.x, v0.y, v0.z, v0.w,
                     v1.x, v1.y, v1.z, v1.w,
                     v2.x, v2.y, v2.z, v2.w };

    // a = 2*atan(tanh(x))  =>  sin a = tanh(2x), cos a = sech(2x).
    // With u = e^{2x}:  cos a = 2u/(u^2+1),  sin a = (u^2-1)/(u^2+1).
    float uu[NQ], u2[NQ], d[NQ];
#pragma unroll
    for (int q = 0; q < NQ; q++) {
        float xc = fminf(fmaxf(xv[q], -5.0f), 5.0f);   // saturated region anyway
        float u  = ex2f(xc * 2.8853900817779268f);     // 2*log2(e)
        uu[q] = u;
        u2[q] = u * u;
        d[q]  = u2[q] + 1.0f;
    }

    // Grouped reciprocals: 3 MUFU.RCP instead of 12.
    // Max d ~ e^20+1 ~ 4.9e8; product of 4 ~ 5.5e34 < FLT_MAX.
    float inv[NQ];
#pragma unroll
    for (int g = 0; g < NQ; g += 4) {
        float d01 = d[g]     * d[g + 1];
        float d23 = d[g + 2] * d[g + 3];
        float ia  = rcpf(d01 * d23);
        float i01 = ia * d23;
        float i23 = ia * d01;
        inv[g]     = i01 * d[g + 1];
        inv[g + 1] = i01 * d[g];
        inv[g + 2] = i23 * d[g + 3];
        inv[g + 3] = i23 * d[g + 2];
    }

    float ca[NQ], sa[NQ];
#pragma unroll
    for (int q = 0; q < NQ; q++) {
        ca[q] = (uu[q] + uu[q]) * inv[q];
        sa[q] = (u2[q] - 1.0f) * inv[q];
    }

    // P_q = prod_{p<=q} cos a_p
    float P[NQ];
    float prod = 1.0f;
#pragma unroll
    for (int q = 0; q < NQ; q++) {
        prod *= ca[q];
        P[q] = prod;
    }

    __syncthreads();   // sincos smem ready; latency hidden behind math above

    // out_q = cos(w_q)*P_q - sin(w_q)*S_q,
    // S_q = sa_q*sa_{q+1} (q<11), S_11 = sa_11
    float o[NQ];
#pragma unroll
    for (int q = 0; q < NQ; q++) {
        float S = (q < NQ - 1) ? sa[q] * sa[q + 1] : sa[q];
        o[q] = s_cw[q] * P[q] - s_sw[q] * S;
    }

    if (active) {
        float4* orow = reinterpret_cast<float4*>(out + (size_t)b * NQ);
        orow[0] = make_float4(o[0], o[1], o[2],  o[3]);
        orow[1] = make_float4(o[4], o[5], o[6],  o[7]);
        orow[2] = make_float4(o[8], o[9], o[10], o[11]);
    }
}

extern "C" void kernel_launch(void* const* d_in, const int* in_sizes, int n_in,
                              void* d_out, int out_size)
{
    const float* x = (const float*)d_in[0];   // [B, 12]
    const float* w = (const float*)d_in[1];   // [36], only first 12 used
    float* out = (float*)d_out;               // [B, 12]
    int B = in_sizes[0] / NQ;

    int threads = 128;
    int blocks = (B + threads - 1) / threads; // 128 for B=16384
    quantum_layer_kernel<<<blocks, threads>>>(x, w, out, B);
}